// round 1
// baseline (speedup 1.0000x reference)
#include <cuda_runtime.h>
#include <math.h>

#define SD 2048
#define ED 1024
#define HD 16
#define DD 64
#define BD 2
#define BH (BD*HD)     /* 32 */
#define ROWS (BD*SD)   /* 4096 */
#define BHS (BH*SD)    /* 65536 */

// ---------------- scratch (device globals; no allocation allowed) ----------------
__device__ float g_Q[(size_t)BHS * DD];
__device__ float g_K[(size_t)BHS * DD];
__device__ float g_V[(size_t)BHS * DD];
__device__ float g_qM[(size_t)BHS * DD];
__device__ float g_qMq[BHS];
__device__ float g_kMk[BHS];
__device__ float g_rowm[BHS];
__device__ float g_rowl[BHS];
__device__ float g_ctx[(size_t)ROWS * ED];
__device__ float g_tmp[(size_t)ROWS * ED];

// ---------------- 128x128x8 SGEMM: C = A * B^T (+bias, epilogue variants) --------
// A: [M,K] row-major, Bw: [N,K] row-major.
// MODE 0: write to [B,H,S,D] layout (QKV projection), v = acc + bias[c]
// MODE 1: write C[r*ED+c] = acc + bias[c] + resid[r*ED+c]
template <int MODE>
__global__ __launch_bounds__(256) void sgemm128(
    const float* __restrict__ A, const float* __restrict__ Bw,
    float* __restrict__ C, int K,
    const float* __restrict__ bias, const float* __restrict__ resid)
{
    __shared__ float As[8][128];
    __shared__ float Bs[8][128];
    const int t  = threadIdx.x;
    const int tx = t & 15, ty = t >> 4;
    const int row0 = blockIdx.y * 128, col0 = blockIdx.x * 128;
    const int lr = t >> 1, lq = (t & 1) * 4;
    const float* Ap = A  + (size_t)(row0 + lr) * K + lq;
    const float* Bp = Bw + (size_t)(col0 + lr) * K + lq;

    float acc[8][8];
#pragma unroll
    for (int i = 0; i < 8; i++)
#pragma unroll
        for (int j = 0; j < 8; j++) acc[i][j] = 0.f;

    float4 av = *(const float4*)Ap;
    float4 bv = *(const float4*)Bp;
    for (int k0 = 0; k0 < K; k0 += 8) {
        As[lq + 0][lr] = av.x; As[lq + 1][lr] = av.y; As[lq + 2][lr] = av.z; As[lq + 3][lr] = av.w;
        Bs[lq + 0][lr] = bv.x; Bs[lq + 1][lr] = bv.y; Bs[lq + 2][lr] = bv.z; Bs[lq + 3][lr] = bv.w;
        __syncthreads();
        if (k0 + 8 < K) {
            av = *(const float4*)(Ap + k0 + 8);
            bv = *(const float4*)(Bp + k0 + 8);
        }
#pragma unroll
        for (int kk = 0; kk < 8; kk++) {
            float a[8], b[8];
            *(float4*)(a)     = *(const float4*)&As[kk][ty * 8];
            *(float4*)(a + 4) = *(const float4*)&As[kk][ty * 8 + 4];
            *(float4*)(b)     = *(const float4*)&Bs[kk][tx * 8];
            *(float4*)(b + 4) = *(const float4*)&Bs[kk][tx * 8 + 4];
#pragma unroll
            for (int i = 0; i < 8; i++)
#pragma unroll
                for (int j = 0; j < 8; j++) acc[i][j] = fmaf(a[i], b[j], acc[i][j]);
        }
        __syncthreads();
    }

#pragma unroll
    for (int i = 0; i < 8; i++) {
        const int r = row0 + ty * 8 + i;
#pragma unroll
        for (int j = 0; j < 8; j++) {
            const int c = col0 + tx * 8 + j;
            float v = acc[i][j] + bias[c];
            if (MODE == 0) {
                const int b_ = r >> 11, s_ = r & (SD - 1);
                const int h_ = c >> 6,  d_ = c & 63;
                C[(((size_t)(b_ * HD + h_)) * SD + s_) * DD + d_] = v;
            } else {
                const size_t idx = (size_t)r * ED + c;
                C[idx] = v + resid[idx];
            }
        }
    }
}

// ---------------- qM = Q*M, qMq = sum(Q*qM), kMk = sum(K*kM) ---------------------
__global__ __launch_bounds__(128) void qm_kernel(const float* __restrict__ M)
{
    __shared__ float Ms[64][64];
    const int t = threadIdx.x;
    for (int idx = t; idx < 64 * 64 / 4; idx += 128)
        ((float4*)Ms)[idx] = ((const float4*)M)[idx];
    const int row = blockIdx.x * 128 + t;
    const bool isQ = (blockIdx.y == 0);
    const float* src = (isQ ? g_Q : g_K) + (size_t)row * DD;

    float r[64];
    const float4* s4 = (const float4*)src;
#pragma unroll
    for (int i = 0; i < 16; i++) {
        float4 v = s4[i];
        r[4 * i + 0] = v.x; r[4 * i + 1] = v.y; r[4 * i + 2] = v.z; r[4 * i + 3] = v.w;
    }
    __syncthreads();

    float dot = 0.f;
#pragma unroll
    for (int e = 0; e < 64; e++) {
        float acc = 0.f;
#pragma unroll
        for (int d = 0; d < 64; d++) acc = fmaf(r[d], Ms[d][e], acc);
        if (isQ) g_qM[(size_t)row * DD + e] = acc;
        dot = fmaf(r[e], acc, dot);
    }
    if (isQ) g_qMq[row] = dot; else g_kMk[row] = dot;
}

// ---------------- scores = 8*(2*qMk - qMq - kMk); online (m,l) per row ----------
__global__ __launch_bounds__(256) void scores_kernel(float* __restrict__ sc_out)
{
    extern __shared__ float sm[];
    float (*qMT)[128] = (float(*)[128])sm;            // [64][128]
    float (*KT)[128]  = (float(*)[128])(sm + 64 * 128);
    __shared__ float qq[128], kks[128], m_s[128], l_s[128];

    const int bh = blockIdx.y;
    const int q0 = blockIdx.x * 128;
    const float* qMb = g_qM + (size_t)bh * SD * DD;
    const float* Kb  = g_K  + (size_t)bh * SD * DD;
    float* sc = sc_out + (size_t)bh * SD * SD;
    const int t = threadIdx.x, tx = t & 15, ty = t >> 4;

    for (int idx = t; idx < 128 * 16; idx += 256) {
        int r = idx >> 4, c4 = (idx & 15) << 2;
        float4 v = *(const float4*)(qMb + (size_t)(q0 + r) * DD + c4);
        qMT[c4 + 0][r] = v.x; qMT[c4 + 1][r] = v.y; qMT[c4 + 2][r] = v.z; qMT[c4 + 3][r] = v.w;
    }
    if (t < 128) { qq[t] = g_qMq[bh * SD + q0 + t]; m_s[t] = -INFINITY; l_s[t] = 0.f; }

    for (int n0 = 0; n0 < SD; n0 += 128) {
        __syncthreads();  // KT reuse + first-iter qMT/qq visibility
        for (int idx = t; idx < 128 * 16; idx += 256) {
            int r = idx >> 4, c4 = (idx & 15) << 2;
            float4 v = *(const float4*)(Kb + (size_t)(n0 + r) * DD + c4);
            KT[c4 + 0][r] = v.x; KT[c4 + 1][r] = v.y; KT[c4 + 2][r] = v.z; KT[c4 + 3][r] = v.w;
        }
        if (t < 128) kks[t] = g_kMk[bh * SD + n0 + t];
        __syncthreads();

        float acc[8][8];
#pragma unroll
        for (int i = 0; i < 8; i++)
#pragma unroll
            for (int j = 0; j < 8; j++) acc[i][j] = 0.f;

#pragma unroll
        for (int k = 0; k < 64; k++) {
            float a[8], b[8];
            *(float4*)(a)     = *(const float4*)&qMT[k][ty * 8];
            *(float4*)(a + 4) = *(const float4*)&qMT[k][ty * 8 + 4];
            *(float4*)(b)     = *(const float4*)&KT[k][tx * 8];
            *(float4*)(b + 4) = *(const float4*)&KT[k][tx * 8 + 4];
#pragma unroll
            for (int i = 0; i < 8; i++)
#pragma unroll
                for (int j = 0; j < 8; j++) acc[i][j] = fmaf(a[i], b[j], acc[i][j]);
        }

#pragma unroll
        for (int i = 0; i < 8; i++) {
            const int row = ty * 8 + i;
            const float qqv = qq[row];
            float s[8];
            float rmax = -INFINITY;
#pragma unroll
            for (int j = 0; j < 8; j++) {
                float v = 8.f * (2.f * acc[i][j] - qqv - kks[tx * 8 + j]);
                s[j] = v;
                rmax = fmaxf(rmax, v);
            }
            float* dst = sc + (size_t)(q0 + row) * SD + n0 + tx * 8;
            *(float4*)dst       = make_float4(s[0], s[1], s[2], s[3]);
            *(float4*)(dst + 4) = make_float4(s[4], s[5], s[6], s[7]);
#pragma unroll
            for (int o = 8; o > 0; o >>= 1)
                rmax = fmaxf(rmax, __shfl_xor_sync(0xffffffffu, rmax, o, 16));
            const float mold = m_s[row];
            const float mnew = fmaxf(mold, rmax);
            float se = 0.f;
#pragma unroll
            for (int j = 0; j < 8; j++) se += __expf(s[j] - mnew);
#pragma unroll
            for (int o = 8; o > 0; o >>= 1)
                se += __shfl_xor_sync(0xffffffffu, se, o, 16);
            if (tx == 0) { l_s[row] = l_s[row] * __expf(mold - mnew) + se; m_s[row] = mnew; }
        }
    }
    __syncthreads();
    if (t < 128) { g_rowm[bh * SD + q0 + t] = m_s[t]; g_rowl[bh * SD + q0 + t] = l_s[t]; }
}

// ---------------- attn = softmax(scores) in-place; ctx = attn @ V ----------------
__global__ __launch_bounds__(256) void attn_ctx_kernel(float* __restrict__ attn)
{
    __shared__ float Ps[32][128];
    __shared__ float Vs[32][64];
    __shared__ float m_s[128], il_s[128];
    const int bh = blockIdx.y, q0 = blockIdx.x * 128;
    const int b = bh >> 4, h = bh & 15;
    float* sc = attn + (size_t)bh * SD * SD;
    const float* Vb = g_V + (size_t)bh * SD * DD;
    const int t = threadIdx.x, tx = t & 15, ty = t >> 4;

    if (t < 128) {
        m_s[t]  = g_rowm[bh * SD + q0 + t];
        il_s[t] = 1.f / g_rowl[bh * SD + q0 + t];
    }
    __syncthreads();

    float acc[8][4];
#pragma unroll
    for (int i = 0; i < 8; i++)
#pragma unroll
        for (int j = 0; j < 4; j++) acc[i][j] = 0.f;

    for (int k0 = 0; k0 < SD; k0 += 32) {
        for (int idx = t; idx < 128 * 8; idx += 256) {
            int r = idx >> 3, c4 = (idx & 7) << 2;
            size_t g = (size_t)(q0 + r) * SD + k0 + c4;
            float4 v = *(const float4*)(sc + g);
            const float mm = m_s[r], il = il_s[r];
            v.x = __expf(v.x - mm) * il;
            v.y = __expf(v.y - mm) * il;
            v.z = __expf(v.z - mm) * il;
            v.w = __expf(v.w - mm) * il;
            *(float4*)(sc + g) = v;   // final attn value
            Ps[c4 + 0][r] = v.x; Ps[c4 + 1][r] = v.y; Ps[c4 + 2][r] = v.z; Ps[c4 + 3][r] = v.w;
        }
        for (int idx = t; idx < 32 * 16; idx += 256) {
            int r = idx >> 4, c4 = (idx & 15) << 2;
            *(float4*)&Vs[r][c4] = *(const float4*)(Vb + (size_t)(k0 + r) * DD + c4);
        }
        __syncthreads();
#pragma unroll
        for (int kk = 0; kk < 32; kk++) {
            float a[8], bb[4];
            *(float4*)(a)     = *(const float4*)&Ps[kk][ty * 8];
            *(float4*)(a + 4) = *(const float4*)&Ps[kk][ty * 8 + 4];
            *(float4*)bb      = *(const float4*)&Vs[kk][tx * 4];
#pragma unroll
            for (int i = 0; i < 8; i++)
#pragma unroll
                for (int j = 0; j < 4; j++) acc[i][j] = fmaf(a[i], bb[j], acc[i][j]);
        }
        __syncthreads();
    }
#pragma unroll
    for (int i = 0; i < 8; i++) {
        const int s_ = q0 + ty * 8 + i;
        float4 o4 = make_float4(acc[i][0], acc[i][1], acc[i][2], acc[i][3]);
        *(float4*)(g_ctx + ((size_t)b * SD + s_) * ED + h * DD + tx * 4) = o4;
    }
}

// ---------------- LayerNorm ------------------------------------------------------
__global__ __launch_bounds__(256) void ln_kernel(
    const float* __restrict__ gamma, const float* __restrict__ beta,
    float* __restrict__ out)
{
    const int row = blockIdx.x;
    const int t = threadIdx.x;
    float4 v = *(const float4*)(g_tmp + (size_t)row * ED + t * 4);
    float s  = v.x + v.y + v.z + v.w;
    float s2 = v.x * v.x + v.y * v.y + v.z * v.z + v.w * v.w;
#pragma unroll
    for (int o = 16; o > 0; o >>= 1) {
        s  += __shfl_xor_sync(0xffffffffu, s, o);
        s2 += __shfl_xor_sync(0xffffffffu, s2, o);
    }
    __shared__ float ws[8], ws2[8];
    if ((t & 31) == 0) { ws[t >> 5] = s; ws2[t >> 5] = s2; }
    __syncthreads();
    if (t < 32) {
        float a = (t < 8) ? ws[t] : 0.f;
        float b = (t < 8) ? ws2[t] : 0.f;
#pragma unroll
        for (int o = 4; o > 0; o >>= 1) {
            a += __shfl_xor_sync(0xffffffffu, a, o);
            b += __shfl_xor_sync(0xffffffffu, b, o);
        }
        if (t == 0) { ws[0] = a; ws2[0] = b; }
    }
    __syncthreads();
    const float mu  = ws[0] * (1.f / ED);
    const float var = ws2[0] * (1.f / ED) - mu * mu;
    const float inv = rsqrtf(var + 1e-5f);
    const int c = t * 4;
    float4 g  = *(const float4*)(gamma + c);
    float4 be = *(const float4*)(beta + c);
    float4 o4;
    o4.x = (v.x - mu) * inv * g.x + be.x;
    o4.y = (v.y - mu) * inv * g.y + be.y;
    o4.z = (v.z - mu) * inv * g.z + be.z;
    o4.w = (v.w - mu) * inv * g.w + be.w;
    *(float4*)(out + (size_t)row * ED + c) = o4;
}

// ---------------- launch ---------------------------------------------------------
extern "C" void kernel_launch(void* const* d_in, const int* in_sizes, int n_in,
                              void* d_out, int out_size)
{
    const float* x     = (const float*)d_in[0];
    const float* Wq    = (const float*)d_in[1];
    const float* bq    = (const float*)d_in[2];
    const float* Wk    = (const float*)d_in[3];
    const float* bk    = (const float*)d_in[4];
    const float* Wv    = (const float*)d_in[5];
    const float* bv    = (const float*)d_in[6];
    const float* M     = (const float*)d_in[7];
    const float* Wo    = (const float*)d_in[8];
    const float* bo    = (const float*)d_in[9];
    const float* gamma = (const float*)d_in[10];
    const float* beta  = (const float*)d_in[11];

    float* outp  = (float*)d_out;
    float* attnp = outp + (size_t)ROWS * ED;   // tuple order: out, then attn

    float *Qp, *Kp, *Vp, *ctxp, *tmpp;
    cudaGetSymbolAddress((void**)&Qp,   g_Q);
    cudaGetSymbolAddress((void**)&Kp,   g_K);
    cudaGetSymbolAddress((void**)&Vp,   g_V);
    cudaGetSymbolAddress((void**)&ctxp, g_ctx);
    cudaGetSymbolAddress((void**)&tmpp, g_tmp);

    cudaFuncSetAttribute(scores_kernel,
                         cudaFuncAttributeMaxDynamicSharedMemorySize, 2 * 64 * 128 * 4);

    dim3 gProj(ED / 128, ROWS / 128);   // (8, 32)
    sgemm128<0><<<gProj, 256>>>(x, Wq, Qp, ED, bq, nullptr);
    sgemm128<0><<<gProj, 256>>>(x, Wk, Kp, ED, bk, nullptr);
    sgemm128<0><<<gProj, 256>>>(x, Wv, Vp, ED, bv, nullptr);

    qm_kernel<<<dim3(BHS / 128, 2), 128>>>(M);

    scores_kernel<<<dim3(SD / 128, BH), 256, 2 * 64 * 128 * 4>>>(attnp);
    attn_ctx_kernel<<<dim3(SD / 128, BH), 256>>>(attnp);

    sgemm128<1><<<gProj, 256>>>(ctxp, Wo, tmpp, ED, bo, x);
    ln_kernel<<<ROWS, 256>>>(gamma, beta, outp);
}

// round 3
// speedup vs baseline: 1.6217x; 1.6217x over previous
#include <cuda_runtime.h>
#include <cuda_fp16.h>
#include <math.h>
#include <stdint.h>

#define SD 2048
#define ED 1024
#define HD 16
#define DD 64
#define BD 2
#define BH (BD*HD)     /* 32 */
#define ROWS (BD*SD)   /* 4096 */
#define BHS (BH*SD)    /* 65536 */

// ---------------- scratch ----------------
__device__ float g_Q[(size_t)BHS * DD];
__device__ float g_K[(size_t)BHS * DD];
__device__ float g_V[(size_t)BHS * DD];
__device__ float g_qM[(size_t)BHS * DD];
__device__ float g_qMq[BHS];
__device__ float g_kMk[BHS];
__device__ float g_rowm[BHS];
__device__ float g_rowl[BHS];
__device__ float g_ctx[(size_t)ROWS * ED];
__device__ float g_tmp[(size_t)ROWS * ED];

// ---------------- mma helpers ----------------
__device__ __forceinline__ void mma16816(float (&c)[4],
    uint32_t a0, uint32_t a1, uint32_t a2, uint32_t a3, uint32_t b0, uint32_t b1)
{
    asm volatile(
        "mma.sync.aligned.m16n8k16.row.col.f32.f16.f16.f32 "
        "{%0,%1,%2,%3}, {%4,%5,%6,%7}, {%8,%9}, {%0,%1,%2,%3};"
        : "+f"(c[0]), "+f"(c[1]), "+f"(c[2]), "+f"(c[3])
        : "r"(a0), "r"(a1), "r"(a2), "r"(a3), "r"(b0), "r"(b1));
}

__device__ __forceinline__ uint32_t ld_u32(const __half* p) {
    return *reinterpret_cast<const uint32_t*>(p);
}

// split x,y into hi fp16 pair (-> ph) and lo fp16 pair (-> pl)
__device__ __forceinline__ void split_st(__half* ph, __half* pl, float x, float y) {
    __half hx = __float2half_rn(x), hy = __float2half_rn(y);
    *reinterpret_cast<__half2*>(ph) = __halves2half2(hx, hy);
    __half lx = __float2half_rn(x - __half2float(hx));
    __half ly = __float2half_rn(y - __half2float(hy));
    *reinterpret_cast<__half2*>(pl) = __halves2half2(lx, ly);
}

// ---------------- 128x128 HGEMM (fp16-split x3): C = A * Bw^T ----------------
// A:[M,K] rm, Bw:[N,K] rm. MODE 0: scatter to [B,H,S,D] +bias. MODE 1: +bias+resid.
template <int MODE>
__global__ __launch_bounds__(256) void hgemm128(
    const float* __restrict__ A, const float* __restrict__ Bw,
    float* __restrict__ C, int K,
    const float* __restrict__ bias, const float* __restrict__ resid)
{
    __shared__ __half Ah[128][40], Al[128][40], Bh[128][40], Bl[128][40];
    const int t = threadIdx.x;
    const int wid = t >> 5, lane = t & 31;
    const int g = lane >> 2, tg = lane & 3;
    const int wr = wid >> 1, wc = wid & 1;
    const int row0 = blockIdx.y * 128, col0 = blockIdx.x * 128;
    const int lr = t >> 1, lq = (t & 1) * 16;
    const float* Ap = A  + (size_t)(row0 + lr) * K + lq;
    const float* Bp = Bw + (size_t)(col0 + lr) * K + lq;

    float acc[2][8][4];
#pragma unroll
    for (int mt = 0; mt < 2; mt++)
#pragma unroll
        for (int nt = 0; nt < 8; nt++)
#pragma unroll
            for (int j = 0; j < 4; j++) acc[mt][nt][j] = 0.f;

    float4 av[4], bv[4];
#pragma unroll
    for (int i = 0; i < 4; i++) { av[i] = *(const float4*)(Ap + i * 4); bv[i] = *(const float4*)(Bp + i * 4); }

    for (int k0 = 0; k0 < K; k0 += 32) {
#pragma unroll
        for (int i = 0; i < 4; i++) {
            split_st(&Ah[lr][lq + 4 * i],     &Al[lr][lq + 4 * i],     av[i].x, av[i].y);
            split_st(&Ah[lr][lq + 4 * i + 2], &Al[lr][lq + 4 * i + 2], av[i].z, av[i].w);
            split_st(&Bh[lr][lq + 4 * i],     &Bl[lr][lq + 4 * i],     bv[i].x, bv[i].y);
            split_st(&Bh[lr][lq + 4 * i + 2], &Bl[lr][lq + 4 * i + 2], bv[i].z, bv[i].w);
        }
        __syncthreads();
        if (k0 + 32 < K) {
#pragma unroll
            for (int i = 0; i < 4; i++) {
                av[i] = *(const float4*)(Ap + k0 + 32 + i * 4);
                bv[i] = *(const float4*)(Bp + k0 + 32 + i * 4);
            }
        }
#pragma unroll
        for (int ks = 0; ks < 2; ks++) {
            const int kb = ks * 16;
            uint32_t ahi[2][4], alo[2][4];
#pragma unroll
            for (int mt = 0; mt < 2; mt++) {
                const int r0 = wr * 32 + mt * 16;
                ahi[mt][0] = ld_u32(&Ah[r0 + g][kb + 2 * tg]);
                ahi[mt][1] = ld_u32(&Ah[r0 + g + 8][kb + 2 * tg]);
                ahi[mt][2] = ld_u32(&Ah[r0 + g][kb + 2 * tg + 8]);
                ahi[mt][3] = ld_u32(&Ah[r0 + g + 8][kb + 2 * tg + 8]);
                alo[mt][0] = ld_u32(&Al[r0 + g][kb + 2 * tg]);
                alo[mt][1] = ld_u32(&Al[r0 + g + 8][kb + 2 * tg]);
                alo[mt][2] = ld_u32(&Al[r0 + g][kb + 2 * tg + 8]);
                alo[mt][3] = ld_u32(&Al[r0 + g + 8][kb + 2 * tg + 8]);
            }
#pragma unroll
            for (int nt = 0; nt < 8; nt++) {
                const int nr = wc * 64 + nt * 8 + g;
                uint32_t bh0 = ld_u32(&Bh[nr][kb + 2 * tg]);
                uint32_t bh1 = ld_u32(&Bh[nr][kb + 2 * tg + 8]);
                uint32_t bl0 = ld_u32(&Bl[nr][kb + 2 * tg]);
                uint32_t bl1 = ld_u32(&Bl[nr][kb + 2 * tg + 8]);
#pragma unroll
                for (int mt = 0; mt < 2; mt++) {
                    mma16816(acc[mt][nt], ahi[mt][0], ahi[mt][1], ahi[mt][2], ahi[mt][3], bh0, bh1);
                    mma16816(acc[mt][nt], ahi[mt][0], ahi[mt][1], ahi[mt][2], ahi[mt][3], bl0, bl1);
                    mma16816(acc[mt][nt], alo[mt][0], alo[mt][1], alo[mt][2], alo[mt][3], bh0, bh1);
                }
            }
        }
        __syncthreads();
    }

#pragma unroll
    for (int mt = 0; mt < 2; mt++) {
        const int rA = row0 + wr * 32 + mt * 16 + g;
        const int rB = rA + 8;
#pragma unroll
        for (int nt = 0; nt < 8; nt++) {
            const int c = col0 + wc * 64 + nt * 8 + 2 * tg;
            const float b0 = bias[c], b1 = bias[c + 1];
            float v00 = acc[mt][nt][0] + b0, v01 = acc[mt][nt][1] + b1;
            float v10 = acc[mt][nt][2] + b0, v11 = acc[mt][nt][3] + b1;
            if (MODE == 0) {
                const int h_ = c >> 6, d_ = c & 63;
                size_t iA = (((size_t)(rA >> 11) * HD + h_) * SD + (rA & (SD - 1))) * DD + d_;
                size_t iB = (((size_t)(rB >> 11) * HD + h_) * SD + (rB & (SD - 1))) * DD + d_;
                *(float2*)&C[iA] = make_float2(v00, v01);
                *(float2*)&C[iB] = make_float2(v10, v11);
            } else {
                size_t iA = (size_t)rA * ED + c;
                size_t iB = (size_t)rB * ED + c;
                float2 r0 = *(const float2*)&resid[iA];
                float2 r1 = *(const float2*)&resid[iB];
                *(float2*)&C[iA] = make_float2(v00 + r0.x, v01 + r0.y);
                *(float2*)&C[iB] = make_float2(v10 + r1.x, v11 + r1.y);
            }
        }
    }
}

// ---------------- qM = Q*M, qMq, kMk ----------------
__global__ __launch_bounds__(128) void qm_kernel(const float* __restrict__ M)
{
    __shared__ float Ms[64][64];
    const int t = threadIdx.x;
    for (int idx = t; idx < 64 * 64 / 4; idx += 128)
        ((float4*)Ms)[idx] = ((const float4*)M)[idx];
    const int row = blockIdx.x * 128 + t;
    const bool isQ = (blockIdx.y == 0);
    const float* src = (isQ ? g_Q : g_K) + (size_t)row * DD;

    float r[64];
    const float4* s4 = (const float4*)src;
#pragma unroll
    for (int i = 0; i < 16; i++) {
        float4 v = s4[i];
        r[4 * i + 0] = v.x; r[4 * i + 1] = v.y; r[4 * i + 2] = v.z; r[4 * i + 3] = v.w;
    }
    __syncthreads();

    float dot = 0.f;
#pragma unroll
    for (int e4 = 0; e4 < 16; e4++) {
        float4 a = make_float4(0.f, 0.f, 0.f, 0.f);
#pragma unroll
        for (int d = 0; d < 64; d++) {
            float4 m4 = *(const float4*)&Ms[d][e4 * 4];
            a.x = fmaf(r[d], m4.x, a.x);
            a.y = fmaf(r[d], m4.y, a.y);
            a.z = fmaf(r[d], m4.z, a.z);
            a.w = fmaf(r[d], m4.w, a.w);
        }
        if (isQ) *(float4*)(g_qM + (size_t)row * DD + e4 * 4) = a;
        dot = fmaf(r[e4 * 4 + 0], a.x, dot);
        dot = fmaf(r[e4 * 4 + 1], a.y, dot);
        dot = fmaf(r[e4 * 4 + 2], a.z, dot);
        dot = fmaf(r[e4 * 4 + 3], a.w, dot);
    }
    if (isQ) g_qMq[row] = dot; else g_kMk[row] = dot;
}

// ---------------- scores (mma): s=8*(2*qMk - qMq - kMk), online (m,l) ----------
__global__ __launch_bounds__(256) void scores_mma(float* __restrict__ sc_out)
{
    extern __shared__ __half smx[];
    __half (*qMh)[72] = (__half(*)[72])smx;
    __half (*qMl)[72] = qMh + 128;
    __half (*Kh)[72]  = qMh + 256;
    __half (*Kl)[72]  = qMh + 384;
    __shared__ float qq[128], kks[128];

    const int bh = blockIdx.y, q0 = blockIdx.x * 128;
    const float* qMb = g_qM + (size_t)bh * SD * DD;
    const float* Kb  = g_K  + (size_t)bh * SD * DD;
    float* sc = sc_out + (size_t)bh * SD * SD;
    const int t = threadIdx.x, wid = t >> 5, lane = t & 31;
    const int g = lane >> 2, tg = lane & 3;
    const int rA = wid * 16 + g, rB = rA + 8;

    for (int idx = t; idx < 128 * 16; idx += 256) {
        int r = idx >> 4, c4 = (idx & 15) << 2;
        float4 v = *(const float4*)(qMb + (size_t)(q0 + r) * DD + c4);
        split_st(&qMh[r][c4],     &qMl[r][c4],     v.x, v.y);
        split_st(&qMh[r][c4 + 2], &qMl[r][c4 + 2], v.z, v.w);
    }
    if (t < 128) qq[t] = g_qMq[bh * SD + q0 + t];

    float mrA = -INFINITY, lrA = 0.f, mrB = -INFINITY, lrB = 0.f;

    for (int n0 = 0; n0 < SD; n0 += 128) {
        __syncthreads();
        for (int idx = t; idx < 128 * 16; idx += 256) {
            int r = idx >> 4, c4 = (idx & 15) << 2;
            float4 v = *(const float4*)(Kb + (size_t)(n0 + r) * DD + c4);
            split_st(&Kh[r][c4],     &Kl[r][c4],     v.x, v.y);
            split_st(&Kh[r][c4 + 2], &Kl[r][c4 + 2], v.z, v.w);
        }
        if (t < 128) kks[t] = g_kMk[bh * SD + n0 + t];
        __syncthreads();

        float acc[16][4];
#pragma unroll
        for (int nt = 0; nt < 16; nt++)
#pragma unroll
            for (int j = 0; j < 4; j++) acc[nt][j] = 0.f;

#pragma unroll
        for (int kb = 0; kb < 64; kb += 16) {
            uint32_t ah0 = ld_u32(&qMh[rA][kb + 2 * tg]);
            uint32_t ah1 = ld_u32(&qMh[rB][kb + 2 * tg]);
            uint32_t ah2 = ld_u32(&qMh[rA][kb + 2 * tg + 8]);
            uint32_t ah3 = ld_u32(&qMh[rB][kb + 2 * tg + 8]);
            uint32_t al0 = ld_u32(&qMl[rA][kb + 2 * tg]);
            uint32_t al1 = ld_u32(&qMl[rB][kb + 2 * tg]);
            uint32_t al2 = ld_u32(&qMl[rA][kb + 2 * tg + 8]);
            uint32_t al3 = ld_u32(&qMl[rB][kb + 2 * tg + 8]);
#pragma unroll
            for (int nt = 0; nt < 16; nt++) {
                const int nr = nt * 8 + g;
                uint32_t bh0 = ld_u32(&Kh[nr][kb + 2 * tg]);
                uint32_t bh1 = ld_u32(&Kh[nr][kb + 2 * tg + 8]);
                uint32_t bl0 = ld_u32(&Kl[nr][kb + 2 * tg]);
                uint32_t bl1 = ld_u32(&Kl[nr][kb + 2 * tg + 8]);
                mma16816(acc[nt], ah0, ah1, ah2, ah3, bh0, bh1);
                mma16816(acc[nt], ah0, ah1, ah2, ah3, bl0, bl1);
                mma16816(acc[nt], al0, al1, al2, al3, bh0, bh1);
            }
        }

        const float qvA = qq[rA], qvB = qq[rB];
        float mA = -INFINITY, mB = -INFINITY;
#pragma unroll
        for (int nt = 0; nt < 16; nt++) {
            const float k0v = kks[nt * 8 + 2 * tg], k1v = kks[nt * 8 + 2 * tg + 1];
            float s0 = 8.f * (2.f * acc[nt][0] - qvA - k0v);
            float s1 = 8.f * (2.f * acc[nt][1] - qvA - k1v);
            float s2 = 8.f * (2.f * acc[nt][2] - qvB - k0v);
            float s3 = 8.f * (2.f * acc[nt][3] - qvB - k1v);
            acc[nt][0] = s0; acc[nt][1] = s1; acc[nt][2] = s2; acc[nt][3] = s3;
            *(float2*)(sc + (size_t)(q0 + rA) * SD + n0 + nt * 8 + 2 * tg) = make_float2(s0, s1);
            *(float2*)(sc + (size_t)(q0 + rB) * SD + n0 + nt * 8 + 2 * tg) = make_float2(s2, s3);
            mA = fmaxf(mA, fmaxf(s0, s1));
            mB = fmaxf(mB, fmaxf(s2, s3));
        }
        mA = fmaxf(mA, __shfl_xor_sync(0xffffffffu, mA, 1));
        mA = fmaxf(mA, __shfl_xor_sync(0xffffffffu, mA, 2));
        mB = fmaxf(mB, __shfl_xor_sync(0xffffffffu, mB, 1));
        mB = fmaxf(mB, __shfl_xor_sync(0xffffffffu, mB, 2));
        const float mnA = fmaxf(mrA, mA), mnB = fmaxf(mrB, mB);
        float seA = 0.f, seB = 0.f;
#pragma unroll
        for (int nt = 0; nt < 16; nt++) {
            seA += __expf(acc[nt][0] - mnA) + __expf(acc[nt][1] - mnA);
            seB += __expf(acc[nt][2] - mnB) + __expf(acc[nt][3] - mnB);
        }
        seA += __shfl_xor_sync(0xffffffffu, seA, 1);
        seA += __shfl_xor_sync(0xffffffffu, seA, 2);
        seB += __shfl_xor_sync(0xffffffffu, seB, 1);
        seB += __shfl_xor_sync(0xffffffffu, seB, 2);
        lrA = lrA * __expf(mrA - mnA) + seA; mrA = mnA;
        lrB = lrB * __expf(mrB - mnB) + seB; mrB = mnB;
    }
    if (tg == 0) {
        g_rowm[bh * SD + q0 + rA] = mrA; g_rowl[bh * SD + q0 + rA] = lrA;
        g_rowm[bh * SD + q0 + rB] = mrB; g_rowl[bh * SD + q0 + rB] = lrB;
    }
}

// ---------------- attn=softmax in-place; ctx = attn @ V (mma) --------------------
__global__ __launch_bounds__(256) void attn_ctx_mma(float* __restrict__ attn)
{
    __shared__ __half Ph[128][40], Pl[128][40], Vh[64][40], Vl[64][40];
    __shared__ float m_s[128], il_s[128];
    const int bh = blockIdx.y, q0 = blockIdx.x * 128;
    const int b = bh >> 4, h = bh & 15;
    float* sc = attn + (size_t)bh * SD * SD;
    const float* Vb = g_V + (size_t)bh * SD * DD;
    const int t = threadIdx.x, wid = t >> 5, lane = t & 31;
    const int g = lane >> 2, tg = lane & 3;
    const int rA = wid * 16 + g, rB = rA + 8;

    if (t < 128) {
        m_s[t]  = g_rowm[bh * SD + q0 + t];
        il_s[t] = 1.f / g_rowl[bh * SD + q0 + t];
    }
    __syncthreads();

    float acc[8][4];
#pragma unroll
    for (int nt = 0; nt < 8; nt++)
#pragma unroll
        for (int j = 0; j < 4; j++) acc[nt][j] = 0.f;

    for (int k0 = 0; k0 < SD; k0 += 32) {
        for (int idx = t; idx < 128 * 8; idx += 256) {
            int r = idx >> 3, c4 = (idx & 7) << 2;
            size_t ga = (size_t)(q0 + r) * SD + k0 + c4;
            float4 v = *(const float4*)(sc + ga);
            const float mm = m_s[r], il = il_s[r];
            v.x = __expf(v.x - mm) * il;
            v.y = __expf(v.y - mm) * il;
            v.z = __expf(v.z - mm) * il;
            v.w = __expf(v.w - mm) * il;
            *(float4*)(sc + ga) = v;
            split_st(&Ph[r][c4],     &Pl[r][c4],     v.x, v.y);
            split_st(&Ph[r][c4 + 2], &Pl[r][c4 + 2], v.z, v.w);
        }
        for (int idx = t; idx < 32 * 16; idx += 256) {
            int r = idx >> 4, c4 = (idx & 15) << 2;
            float4 v = *(const float4*)(Vb + (size_t)(k0 + r) * DD + c4);
            float vv[4] = {v.x, v.y, v.z, v.w};
#pragma unroll
            for (int j = 0; j < 4; j++) {
                __half hv = __float2half_rn(vv[j]);
                Vh[c4 + j][r] = hv;
                Vl[c4 + j][r] = __float2half_rn(vv[j] - __half2float(hv));
            }
        }
        __syncthreads();
#pragma unroll
        for (int kb = 0; kb < 32; kb += 16) {
            uint32_t ah0 = ld_u32(&Ph[rA][kb + 2 * tg]);
            uint32_t ah1 = ld_u32(&Ph[rB][kb + 2 * tg]);
            uint32_t ah2 = ld_u32(&Ph[rA][kb + 2 * tg + 8]);
            uint32_t ah3 = ld_u32(&Ph[rB][kb + 2 * tg + 8]);
            uint32_t al0 = ld_u32(&Pl[rA][kb + 2 * tg]);
            uint32_t al1 = ld_u32(&Pl[rB][kb + 2 * tg]);
            uint32_t al2 = ld_u32(&Pl[rA][kb + 2 * tg + 8]);
            uint32_t al3 = ld_u32(&Pl[rB][kb + 2 * tg + 8]);
#pragma unroll
            for (int nt = 0; nt < 8; nt++) {
                const int nr = nt * 8 + g;
                uint32_t bh0 = ld_u32(&Vh[nr][kb + 2 * tg]);
                uint32_t bh1 = ld_u32(&Vh[nr][kb + 2 * tg + 8]);
                uint32_t bl0 = ld_u32(&Vl[nr][kb + 2 * tg]);
                uint32_t bl1 = ld_u32(&Vl[nr][kb + 2 * tg + 8]);
                mma16816(acc[nt], ah0, ah1, ah2, ah3, bh0, bh1);
                mma16816(acc[nt], ah0, ah1, ah2, ah3, bl0, bl1);
                mma16816(acc[nt], al0, al1, al2, al3, bh0, bh1);
            }
        }
        __syncthreads();
    }
#pragma unroll
    for (int nt = 0; nt < 8; nt++) {
        const int c = h * DD + nt * 8 + 2 * tg;
        *(float2*)&g_ctx[((size_t)b * SD + q0 + rA) * ED + c] = make_float2(acc[nt][0], acc[nt][1]);
        *(float2*)&g_ctx[((size_t)b * SD + q0 + rB) * ED + c] = make_float2(acc[nt][2], acc[nt][3]);
    }
}

// ---------------- LayerNorm ------------------------------------------------------
__global__ __launch_bounds__(256) void ln_kernel(
    const float* __restrict__ gamma, const float* __restrict__ beta,
    float* __restrict__ out)
{
    const int row = blockIdx.x;
    const int t = threadIdx.x;
    float4 v = *(const float4*)(g_tmp + (size_t)row * ED + t * 4);
    float s  = v.x + v.y + v.z + v.w;
    float s2 = v.x * v.x + v.y * v.y + v.z * v.z + v.w * v.w;
#pragma unroll
    for (int o = 16; o > 0; o >>= 1) {
        s  += __shfl_xor_sync(0xffffffffu, s, o);
        s2 += __shfl_xor_sync(0xffffffffu, s2, o);
    }
    __shared__ float ws[8], ws2[8];
    if ((t & 31) == 0) { ws[t >> 5] = s; ws2[t >> 5] = s2; }
    __syncthreads();
    if (t < 32) {
        float a = (t < 8) ? ws[t] : 0.f;
        float b = (t < 8) ? ws2[t] : 0.f;
#pragma unroll
        for (int o = 4; o > 0; o >>= 1) {
            a += __shfl_xor_sync(0xffffffffu, a, o);
            b += __shfl_xor_sync(0xffffffffu, b, o);
        }
        if (t == 0) { ws[0] = a; ws2[0] = b; }
    }
    __syncthreads();
    const float mu  = ws[0] * (1.f / ED);
    const float var = ws2[0] * (1.f / ED) - mu * mu;
    const float inv = rsqrtf(var + 1e-5f);
    const int c = t * 4;
    float4 ga = *(const float4*)(gamma + c);
    float4 be = *(const float4*)(beta + c);
    float4 o4;
    o4.x = (v.x - mu) * inv * ga.x + be.x;
    o4.y = (v.y - mu) * inv * ga.y + be.y;
    o4.z = (v.z - mu) * inv * ga.z + be.z;
    o4.w = (v.w - mu) * inv * ga.w + be.w;
    *(float4*)(out + (size_t)row * ED + c) = o4;
}

// ---------------- launch ---------------------------------------------------------
extern "C" void kernel_launch(void* const* d_in, const int* in_sizes, int n_in,
                              void* d_out, int out_size)
{
    const float* x     = (const float*)d_in[0];
    const float* Wq    = (const float*)d_in[1];
    const float* bq    = (const float*)d_in[2];
    const float* Wk    = (const float*)d_in[3];
    const float* bk    = (const float*)d_in[4];
    const float* Wv    = (const float*)d_in[5];
    const float* bv    = (const float*)d_in[6];
    const float* M     = (const float*)d_in[7];
    const float* Wo    = (const float*)d_in[8];
    const float* bo    = (const float*)d_in[9];
    const float* gamma = (const float*)d_in[10];
    const float* beta  = (const float*)d_in[11];

    float* outp  = (float*)d_out;
    float* attnp = outp + (size_t)ROWS * ED;   // tuple order: out, then attn

    float *Qp, *Kp, *Vp, *ctxp, *tmpp;
    cudaGetSymbolAddress((void**)&Qp,   g_Q);
    cudaGetSymbolAddress((void**)&Kp,   g_K);
    cudaGetSymbolAddress((void**)&Vp,   g_V);
    cudaGetSymbolAddress((void**)&ctxp, g_ctx);
    cudaGetSymbolAddress((void**)&tmpp, g_tmp);

    cudaFuncSetAttribute(scores_mma,
                         cudaFuncAttributeMaxDynamicSharedMemorySize, 4 * 128 * 72 * 2);

    dim3 gProj(ED / 128, ROWS / 128);   // (8, 32)
    hgemm128<0><<<gProj, 256>>>(x, Wq, Qp, ED, bq, nullptr);
    hgemm128<0><<<gProj, 256>>>(x, Wk, Kp, ED, bk, nullptr);
    hgemm128<0><<<gProj, 256>>>(x, Wv, Vp, ED, bv, nullptr);

    qm_kernel<<<dim3(BHS / 128, 2), 128>>>(M);

    scores_mma<<<dim3(SD / 128, BH), 256, 4 * 128 * 72 * 2>>>(attnp);
    attn_ctx_mma<<<dim3(SD / 128, BH), 256>>>(attnp);

    hgemm128<1><<<gProj, 256>>>(ctxp, Wo, tmpp, ED, bo, x);
    ln_kernel<<<ROWS, 256>>>(gamma, beta, outp);
}